// round 1
// baseline (speedup 1.0000x reference)
#include <cuda_runtime.h>
#include <cuda_bf16.h>
#include <math.h>

#define BQ        16384
#define OBJ_FEAT  1024
#define PVF_DIM   1024
#define PPF_DIM   64
#define HIDDEN    512
#define OBJ_NUM   1001
#define PRED_NUM  132

// Scratch (allocation-free rule: __device__ globals)
__device__ float g_Hs[(size_t)BQ * HIDDEN];
__device__ float g_Ho[(size_t)BQ * HIDDEN];
__device__ float g_Hv[(size_t)BQ * HIDDEN];
__device__ float g_Hp[(size_t)BQ * HIDDEN];

// ---------------- packed f32x2 helpers (sm_103a) ----------------
__device__ __forceinline__ void ffma2(unsigned long long& d,
                                      unsigned long long a,
                                      unsigned long long b) {
    asm("fma.rn.f32x2 %0, %1, %2, %0;" : "+l"(d) : "l"(a), "l"(b));
}
__device__ __forceinline__ unsigned long long pack2(float x, float y) {
    unsigned long long r;
    asm("mov.b64 %0, {%1, %2};" : "=l"(r) : "f"(x), "f"(y));
    return r;
}
__device__ __forceinline__ void unpack2(unsigned long long v, float& lo, float& hi) {
    asm("mov.b64 {%0, %1}, %2;" : "=f"(lo), "=f"(hi) : "l"(v));
}

// ---------------- generic 128x128x16 fp32 GEMM ----------------
// C[M,N] = epi( A[M,K] @ B[K,N] )
// EPI: 0 = none, 1 = +bias then ReLU, 2 = + so2p[gather(gt_s,gt_o)] * exp(factor)
// CONCAT: A is [M,K1] (stride K1) for k<K1, A2 is [M,K-K1] for k>=K1
template <int EPI, bool CONCAT>
__global__ void __launch_bounds__(256, 2)
gemm128(const float* __restrict__ A, const float* __restrict__ A2,
        const float* __restrict__ Bm, const float* __restrict__ bias,
        float* __restrict__ C,
        int M, int N, int K, int K1,
        const int* __restrict__ gts, const int* __restrict__ gto,
        const float* __restrict__ so2p, const float* __restrict__ sof)
{
    __shared__ __align__(16) float As[16][128];
    __shared__ __align__(16) float Bs[16][128];

    const int tid = threadIdx.x;
    const int tx = tid & 15;      // n-dim 0..15
    const int ty = tid >> 4;      // m-dim 0..15
    const int m0 = blockIdx.y * 128;
    const int n0 = blockIdx.x * 128;

    const bool vecB = ((N & 3) == 0) && (n0 + 128 <= N);

    // accumulators: 4 row-pairs x 8 cols, each ull = two fp32 (row r, row r+1)
    unsigned long long acc[4][8];
#pragma unroll
    for (int p = 0; p < 4; p++)
#pragma unroll
        for (int j = 0; j < 8; j++) acc[p][j] = 0ull;

    float ra[8], rb[8];
    const int aRow = tid & 127;
    const int aKq0 = tid >> 7;      // 0 or 1; second chunk adds +2

    // ---- global loaders into staging regs ----
    auto loadA = [&](int k0) {
#pragma unroll
        for (int i = 0; i < 2; i++) {
            const int kq = aKq0 + 2 * i;
            const int gm = m0 + aRow;
            const int kb = k0 + kq * 4;
            if (CONCAT) {
#pragma unroll
                for (int j = 0; j < 4; j++) {
                    const int kk = kb + j;
                    ra[i * 4 + j] = (kk < K1)
                        ? A[(size_t)gm * K1 + kk]
                        : A2[(size_t)gm * (K - K1) + (kk - K1)];
                }
            } else {
                const float4 v = *reinterpret_cast<const float4*>(A + (size_t)gm * K + kb);
                ra[i * 4 + 0] = v.x; ra[i * 4 + 1] = v.y;
                ra[i * 4 + 2] = v.z; ra[i * 4 + 3] = v.w;
            }
        }
    };
    auto loadB = [&](int k0) {
#pragma unroll
        for (int i = 0; i < 2; i++) {
            const int e = tid + i * 256;
            const int krow = e >> 5;
            const int nq = e & 31;
            const int gk = k0 + krow;
            const int n = n0 + nq * 4;
            if (vecB) {
                const float4 v = *reinterpret_cast<const float4*>(Bm + (size_t)gk * N + n);
                rb[i * 4 + 0] = v.x; rb[i * 4 + 1] = v.y;
                rb[i * 4 + 2] = v.z; rb[i * 4 + 3] = v.w;
            } else {
#pragma unroll
                for (int j = 0; j < 4; j++) {
                    const int col = n + j;
                    rb[i * 4 + j] = (col < N) ? Bm[(size_t)gk * N + col] : 0.0f;
                }
            }
        }
    };
    auto stageStore = [&]() {
#pragma unroll
        for (int i = 0; i < 2; i++) {
            const int kq = aKq0 + 2 * i;
#pragma unroll
            for (int j = 0; j < 4; j++) As[kq * 4 + j][aRow] = ra[i * 4 + j];
        }
#pragma unroll
        for (int i = 0; i < 2; i++) {
            const int e = tid + i * 256;
            const int krow = e >> 5;
            const int nq = e & 31;
#pragma unroll
            for (int j = 0; j < 4; j++) Bs[krow][nq * 4 + j] = rb[i * 4 + j];
        }
    };

    // ---- main loop ----
    const int nt = K >> 4;
    loadA(0); loadB(0);
    for (int t = 0; t < nt; t++) {
        stageStore();
        __syncthreads();
        if (t + 1 < nt) { loadA((t + 1) * 16); loadB((t + 1) * 16); }
#pragma unroll
        for (int kk = 0; kk < 16; kk++) {
            const unsigned long long a01 = *reinterpret_cast<const unsigned long long*>(&As[kk][ty * 4]);
            const unsigned long long a23 = *reinterpret_cast<const unsigned long long*>(&As[kk][ty * 4 + 2]);
            const unsigned long long a45 = *reinterpret_cast<const unsigned long long*>(&As[kk][64 + ty * 4]);
            const unsigned long long a67 = *reinterpret_cast<const unsigned long long*>(&As[kk][64 + ty * 4 + 2]);
            const float4 b0 = *reinterpret_cast<const float4*>(&Bs[kk][tx * 4]);
            const float4 b1 = *reinterpret_cast<const float4*>(&Bs[kk][64 + tx * 4]);
            unsigned long long bb[8];
            bb[0] = pack2(b0.x, b0.x); bb[1] = pack2(b0.y, b0.y);
            bb[2] = pack2(b0.z, b0.z); bb[3] = pack2(b0.w, b0.w);
            bb[4] = pack2(b1.x, b1.x); bb[5] = pack2(b1.y, b1.y);
            bb[6] = pack2(b1.z, b1.z); bb[7] = pack2(b1.w, b1.w);
#pragma unroll
            for (int j = 0; j < 8; j++) {
                ffma2(acc[0][j], a01, bb[j]);
                ffma2(acc[1][j], a23, bb[j]);
                ffma2(acc[2][j], a45, bb[j]);
                ffma2(acc[3][j], a67, bb[j]);
            }
        }
        __syncthreads();
    }

    // ---- epilogue ----
    float ef = 1.0f;
    if (EPI == 2) ef = expf(sof[0]);

#pragma unroll
    for (int p = 0; p < 4; p++) {
        const int r = (p < 2) ? (ty * 4 + 2 * p) : (64 + ty * 4 + 2 * (p - 2));
#pragma unroll
        for (int half = 0; half < 2; half++) {
            const int gm = m0 + r + half;
            size_t sob = 0;
            if (EPI == 2) sob = ((size_t)gts[gm] * OBJ_NUM + (size_t)gto[gm]) * PRED_NUM;
#pragma unroll
            for (int j = 0; j < 8; j++) {
                const int col = (j < 4) ? (tx * 4 + j) : (64 + tx * 4 + (j - 4));
                const int gn = n0 + col;
                if (gn < N) {
                    float lo, hi;
                    unpack2(acc[p][j], lo, hi);
                    float v = half ? hi : lo;
                    if (EPI == 1) { v += bias[gn]; v = fmaxf(v, 0.0f); }
                    if (EPI == 2) { v += so2p[sob + gn] * ef; }
                    C[(size_t)gm * N + gn] = v;
                }
            }
        }
    }
}

extern "C" void kernel_launch(void* const* d_in, const int* in_sizes, int n_in,
                              void* d_out, int out_size)
{
    const float* inp_sf  = (const float*)d_in[0];
    const float* inp_of  = (const float*)d_in[1];
    const float* inp_ppf = (const float*)d_in[2];
    const float* inp_pvf = (const float*)d_in[3];
    const int*   gt_s    = (const int*)d_in[4];
    const int*   gt_o    = (const int*)d_in[5];
    const float* W_obj1  = (const float*)d_in[6];
    const float* b_obj1  = (const float*)d_in[7];
    const float* W_obj2  = (const float*)d_in[8];
    const float* W_pvf   = (const float*)d_in[9];
    const float* b_pvf   = (const float*)d_in[10];
    const float* W_pf    = (const float*)d_in[11];
    const float* b_pf    = (const float*)d_in[12];
    const float* W_pred  = (const float*)d_in[13];
    const float* so2p    = (const float*)d_in[14];
    const float* sof     = (const float*)d_in[15];

    float* out   = (float*)d_out;
    float* out_s = out;
    float* out_o = out + (size_t)BQ * OBJ_NUM;
    float* out_p = out + (size_t)2 * BQ * OBJ_NUM;

    float *Hs, *Ho, *Hv, *Hp;
    cudaGetSymbolAddress((void**)&Hs, g_Hs);
    cudaGetSymbolAddress((void**)&Ho, g_Ho);
    cudaGetSymbolAddress((void**)&Hv, g_Hv);
    cudaGetSymbolAddress((void**)&Hp, g_Hp);

    const dim3 blk(256);
    const dim3 gHid(HIDDEN / 128, BQ / 128);                 // (4, 128)
    const dim3 gObj((OBJ_NUM + 127) / 128, BQ / 128);        // (8, 128)
    const dim3 gPrd((PRED_NUM + 127) / 128, BQ / 128);       // (2, 128)

    // Stage 1: hidden layers (bias + ReLU)
    gemm128<1, false><<<gHid, blk>>>(inp_sf,  nullptr, W_obj1, b_obj1, Hs,
                                     BQ, HIDDEN, OBJ_FEAT, 0, nullptr, nullptr, nullptr, nullptr);
    gemm128<1, false><<<gHid, blk>>>(inp_of,  nullptr, W_obj1, b_obj1, Ho,
                                     BQ, HIDDEN, OBJ_FEAT, 0, nullptr, nullptr, nullptr, nullptr);
    gemm128<1, false><<<gHid, blk>>>(inp_pvf, nullptr, W_pvf,  b_pvf,  Hv,
                                     BQ, HIDDEN, PVF_DIM, 0, nullptr, nullptr, nullptr, nullptr);

    // Stage 2: pf_emb = ReLU(concat(Hv, ppf) @ W_pf + b_pf), K = 512 + 64
    gemm128<1, true><<<gHid, blk>>>(Hv, inp_ppf, W_pf, b_pf, Hp,
                                    BQ, HIDDEN, HIDDEN + PPF_DIM, HIDDEN,
                                    nullptr, nullptr, nullptr, nullptr);

    // Stage 3: output scores
    gemm128<0, false><<<gObj, blk>>>(Hs, nullptr, W_obj2, nullptr, out_s,
                                     BQ, OBJ_NUM, HIDDEN, 0, nullptr, nullptr, nullptr, nullptr);
    gemm128<0, false><<<gObj, blk>>>(Ho, nullptr, W_obj2, nullptr, out_o,
                                     BQ, OBJ_NUM, HIDDEN, 0, nullptr, nullptr, nullptr, nullptr);
    gemm128<2, false><<<gPrd, blk>>>(Hp, nullptr, W_pred, nullptr, out_p,
                                     BQ, PRED_NUM, HIDDEN, 0, gt_s, gt_o, so2p, sof);
}

// round 3
// speedup vs baseline: 1.8972x; 1.8972x over previous
#include <cuda_runtime.h>
#include <cuda_bf16.h>
#include <math.h>
#include <stdint.h>

#define BQ        16384
#define OBJ_FEAT  1024
#define PVF_DIM   1024
#define PPF_DIM   64
#define HIDDEN    512
#define OBJ_NUM   1001
#define PRED_NUM  132

#define OBJ_PAD   1024
#define PRED_PAD  256

// ---------------- scratch (__device__ globals; allocation-free rule) --------
__device__ float g_Hs[(size_t)BQ * HIDDEN];
__device__ float g_Ho[(size_t)BQ * HIDDEN];
__device__ float g_Hv[(size_t)BQ * HIDDEN];
__device__ float g_Hp[(size_t)BQ * HIDDEN];
__device__ float g_Wobj2p[(size_t)HIDDEN * OBJ_PAD];   // W_obj2 padded [512,1024]
__device__ float g_Wpredp[(size_t)HIDDEN * PRED_PAD];  // W_pred padded [512,256]

// ---------------- PTX helpers ----------------
__device__ __forceinline__ uint32_t smem_u32(const void* p) {
    uint32_t a;
    asm("{ .reg .u64 t; cvta.to.shared.u64 t, %1; cvt.u32.u64 %0, t; }" : "=r"(a) : "l"(p));
    return a;
}
__device__ __forceinline__ uint32_t cvt_tf32(float f) {
    uint32_t u;
    asm("cvt.rna.tf32.f32 %0, %1;" : "=r"(u) : "f"(f));
    return u;
}
__device__ __forceinline__ void mma_tf32(float* c, const uint32_t* a, const uint32_t* b) {
    asm volatile(
        "mma.sync.aligned.m16n8k8.row.col.f32.tf32.tf32.f32 "
        "{%0,%1,%2,%3}, {%4,%5,%6,%7}, {%8,%9}, {%0,%1,%2,%3};"
        : "+f"(c[0]), "+f"(c[1]), "+f"(c[2]), "+f"(c[3])
        : "r"(a[0]), "r"(a[1]), "r"(a[2]), "r"(a[3]), "r"(b[0]), "r"(b[1]));
}
__device__ __forceinline__ void cp16(uint32_t dst, const float* src) {
    asm volatile("cp.async.cg.shared.global [%0], [%1], 16;" :: "r"(dst), "l"(src));
}
#define CP_COMMIT() asm volatile("cp.async.commit_group;" ::: "memory")
#define CP_WAIT(n)  asm volatile("cp.async.wait_group %0;" :: "n"(n) : "memory")

// ---------------- smem layout ----------------
// As: [128][36] floats per stage (pad 4), Bs: [32][132] floats per stage (pad 4)
#define A_PITCH   36
#define B_PITCH   132
#define A_STAGE   (128 * A_PITCH * 4)          // 18432 B
#define B_STAGE   (32 * B_PITCH * 4)           // 16896 B
#define STAGE_B   (A_STAGE + B_STAGE)          // 35328 B
#define SMEM_BYTES (2 * STAGE_B)               // 70656 B

// ---------------- pad kernel: Wp[k][n] = (n<N) ? W[k][n] : 0 ----------------
__global__ void padW(const float* __restrict__ W, float* __restrict__ Wp,
                     int K, int N, int Npad) {
    int i = blockIdx.x * blockDim.x + threadIdx.x;
    if (i < K * Npad) {
        int k = i / Npad, n = i % Npad;
        Wp[i] = (n < N) ? W[(size_t)k * N + n] : 0.0f;
    }
}

// ---------------- tf32 mma.sync GEMM ----------------
// C[M,N] = epi(A[M,K] @ B[K,N]);  B given with leading dim ldB (padded).
// EPI 0: none | 1: +bias, ReLU | 2: + so2p[gather(gt_s,gt_o)] * exp(f)
template <int EPI, bool CONCAT>
__global__ void __launch_bounds__(256, 2)
mmagemm(const float* __restrict__ A, const float* __restrict__ A2,
        const float* __restrict__ Bm, const float* __restrict__ bias,
        float* __restrict__ C, int N, int ldB, int K,
        const int* __restrict__ gts, const int* __restrict__ gto,
        const float* __restrict__ so2p, const float* __restrict__ sof)
{
    extern __shared__ __align__(16) char smem[];
    float* sA[2] = { (float*)smem, (float*)(smem + STAGE_B) };
    float* sB[2] = { (float*)(smem + A_STAGE), (float*)(smem + STAGE_B + A_STAGE) };
    const uint32_t sbase = smem_u32(smem);

    const int tid  = threadIdx.x;
    const int wid  = tid >> 5, lane = tid & 31;
    const int grp  = lane >> 2, t4 = lane & 3;
    const int wy   = wid >> 2, wx = wid & 3;      // warp grid 2x4
    const int m0   = blockIdx.y * 128;
    const int n0   = blockIdx.x * 128;
    const int mW   = wy * 64, nW = wx * 32;

    float acc[4][4][4];
#pragma unroll
    for (int i = 0; i < 4; i++)
#pragma unroll
        for (int j = 0; j < 4; j++)
#pragma unroll
            for (int r = 0; r < 4; r++) acc[i][j][r] = 0.0f;

    // -------- async loaders --------
    const int aRow = tid >> 1;                 // 128 rows, 2 threads/row
    const int aQ0  = (tid & 1) * 4;            // each thread: 4 float4 (q=aQ0..aQ0+3)
    const int bRow = tid >> 3;                 // 32 rows, 8 threads/row
    const int bQ0  = (tid & 7) * 4;            // each thread: 4 float4

    auto load_stage = [&](int kc, int s) {
        const uint32_t abase = sbase + s * STAGE_B;
        const uint32_t bbase = abase + A_STAGE;
#pragma unroll
        for (int i = 0; i < 4; i++) {
            const int q = aQ0 + i;             // float4 index within 32-float row
            const int k = kc + q * 4;
            const uint32_t dst = abase + (uint32_t)(aRow * A_PITCH + q * 4) * 4u;
            const float* src;
            if (CONCAT)
                src = (k < HIDDEN) ? (A  + (size_t)(m0 + aRow) * HIDDEN + k)
                                   : (A2 + (size_t)(m0 + aRow) * PPF_DIM + (k - HIDDEN));
            else
                src = A + (size_t)(m0 + aRow) * K + k;
            cp16(dst, src);
        }
#pragma unroll
        for (int i = 0; i < 4; i++) {
            const int q = bQ0 + i;             // float4 index within 128-float row
            const uint32_t dst = bbase + (uint32_t)(bRow * B_PITCH + q * 4) * 4u;
            cp16(dst, Bm + (size_t)(kc + bRow) * ldB + n0 + q * 4);
        }
    };

    const int NT = K >> 5;

    load_stage(0, 0); CP_COMMIT();

    for (int t = 0; t < NT; t++) {
        const int s = t & 1;
        if (t + 1 < NT) {
            load_stage((t + 1) << 5, s ^ 1); CP_COMMIT();
            CP_WAIT(1);
        } else {
            CP_WAIT(0);
        }
        __syncthreads();

        const float* As = sA[s];
        const float* Bs = sB[s];
#pragma unroll
        for (int ks = 0; ks < 4; ks++) {
            const int k8 = ks * 8;
            uint32_t af[4][4], bf[4][2];
#pragma unroll
            for (int i = 0; i < 4; i++) {
                const int r = mW + i * 16 + grp;
                af[i][0] = cvt_tf32(As[r * A_PITCH + k8 + t4]);
                af[i][1] = cvt_tf32(As[(r + 8) * A_PITCH + k8 + t4]);
                af[i][2] = cvt_tf32(As[r * A_PITCH + k8 + t4 + 4]);
                af[i][3] = cvt_tf32(As[(r + 8) * A_PITCH + k8 + t4 + 4]);
            }
#pragma unroll
            for (int j = 0; j < 4; j++) {
                const int n = nW + j * 8 + grp;
                bf[j][0] = cvt_tf32(Bs[(k8 + t4) * B_PITCH + n]);
                bf[j][1] = cvt_tf32(Bs[(k8 + t4 + 4) * B_PITCH + n]);
            }
#pragma unroll
            for (int i = 0; i < 4; i++)
#pragma unroll
                for (int j = 0; j < 4; j++)
                    mma_tf32(acc[i][j], af[i], bf[j]);
        }
        __syncthreads();
    }

    // -------- epilogue --------
    float ef = 0.0f;
    if (EPI == 2) ef = expf(sof[0]);

#pragma unroll
    for (int i = 0; i < 4; i++) {
#pragma unroll
        for (int half = 0; half < 2; half++) {
            const int gm = m0 + mW + i * 16 + grp + half * 8;
            size_t sob = 0;
            if (EPI == 2)
                sob = ((size_t)gts[gm] * OBJ_NUM + (size_t)gto[gm]) * (size_t)PRED_NUM;
            float* crow = C + (size_t)gm * N;
#pragma unroll
            for (int j = 0; j < 4; j++) {
                const int gn = n0 + nW + j * 8 + t4 * 2;
#pragma unroll
                for (int e = 0; e < 2; e++) {
                    const int col = gn + e;
                    if (EPI == 1) {
                        float v = acc[i][j][half * 2 + e] + bias[col];
                        crow[col] = fmaxf(v, 0.0f);
                    } else if (EPI == 2) {
                        if (col < N)
                            crow[col] = acc[i][j][half * 2 + e] + so2p[sob + col] * ef;
                    } else {
                        if (col < N)
                            crow[col] = acc[i][j][half * 2 + e];
                    }
                }
            }
        }
    }
}

// ---------------- host ----------------
extern "C" void kernel_launch(void* const* d_in, const int* in_sizes, int n_in,
                              void* d_out, int out_size)
{
    const float* inp_sf  = (const float*)d_in[0];
    const float* inp_of  = (const float*)d_in[1];
    const float* inp_ppf = (const float*)d_in[2];
    const float* inp_pvf = (const float*)d_in[3];
    const int*   gt_s    = (const int*)d_in[4];
    const int*   gt_o    = (const int*)d_in[5];
    const float* W_obj1  = (const float*)d_in[6];
    const float* b_obj1  = (const float*)d_in[7];
    const float* W_obj2  = (const float*)d_in[8];
    const float* W_pvf   = (const float*)d_in[9];
    const float* b_pvf   = (const float*)d_in[10];
    const float* W_pf    = (const float*)d_in[11];
    const float* b_pf    = (const float*)d_in[12];
    const float* W_pred  = (const float*)d_in[13];
    const float* so2p    = (const float*)d_in[14];
    const float* sof     = (const float*)d_in[15];

    float* out   = (float*)d_out;
    float* out_s = out;
    float* out_o = out + (size_t)BQ * OBJ_NUM;
    float* out_p = out + (size_t)2 * BQ * OBJ_NUM;

    float *Hs, *Ho, *Hv, *Hp, *W2p, *Wpp;
    cudaGetSymbolAddress((void**)&Hs,  g_Hs);
    cudaGetSymbolAddress((void**)&Ho,  g_Ho);
    cudaGetSymbolAddress((void**)&Hv,  g_Hv);
    cudaGetSymbolAddress((void**)&Hp,  g_Hp);
    cudaGetSymbolAddress((void**)&W2p, g_Wobj2p);
    cudaGetSymbolAddress((void**)&Wpp, g_Wpredp);

    cudaFuncSetAttribute(mmagemm<1, false>, cudaFuncAttributeMaxDynamicSharedMemorySize, SMEM_BYTES);
    cudaFuncSetAttribute(mmagemm<1, true>,  cudaFuncAttributeMaxDynamicSharedMemorySize, SMEM_BYTES);
    cudaFuncSetAttribute(mmagemm<0, false>, cudaFuncAttributeMaxDynamicSharedMemorySize, SMEM_BYTES);
    cudaFuncSetAttribute(mmagemm<2, false>, cudaFuncAttributeMaxDynamicSharedMemorySize, SMEM_BYTES);

    // pad weights whose N isn't a multiple of 128 (also fixes 16B alignment for obj2)
    padW<<<(HIDDEN * OBJ_PAD + 255) / 256, 256>>>(W_obj2, W2p, HIDDEN, OBJ_NUM, OBJ_PAD);
    padW<<<(HIDDEN * PRED_PAD + 255) / 256, 256>>>(W_pred, Wpp, HIDDEN, PRED_NUM, PRED_PAD);

    const dim3 blk(256);
    const dim3 gHid(HIDDEN / 128, BQ / 128);      // (4, 128)
    const dim3 gObj(OBJ_PAD / 128, BQ / 128);     // (8, 128)
    const dim3 gPrd(PRED_PAD / 128, BQ / 128);    // (2, 128)

    mmagemm<1, false><<<gHid, blk, SMEM_BYTES>>>(inp_sf,  nullptr, W_obj1, b_obj1, Hs,
        HIDDEN, HIDDEN, OBJ_FEAT, nullptr, nullptr, nullptr, nullptr);
    mmagemm<1, false><<<gHid, blk, SMEM_BYTES>>>(inp_of,  nullptr, W_obj1, b_obj1, Ho,
        HIDDEN, HIDDEN, OBJ_FEAT, nullptr, nullptr, nullptr, nullptr);
    mmagemm<1, false><<<gHid, blk, SMEM_BYTES>>>(inp_pvf, nullptr, W_pvf,  b_pvf,  Hv,
        HIDDEN, HIDDEN, PVF_DIM, nullptr, nullptr, nullptr, nullptr);
    mmagemm<1, true><<<gHid, blk, SMEM_BYTES>>>(Hv, inp_ppf, W_pf, b_pf, Hp,
        HIDDEN, HIDDEN, HIDDEN + PPF_DIM, nullptr, nullptr, nullptr, nullptr);
    mmagemm<0, false><<<gObj, blk, SMEM_BYTES>>>(Hs, nullptr, W2p, nullptr, out_s,
        OBJ_NUM, OBJ_PAD, HIDDEN, nullptr, nullptr, nullptr, nullptr);
    mmagemm<0, false><<<gObj, blk, SMEM_BYTES>>>(Ho, nullptr, W2p, nullptr, out_o,
        OBJ_NUM, OBJ_PAD, HIDDEN, nullptr, nullptr, nullptr, nullptr);
    mmagemm<2, false><<<gPrd, blk, SMEM_BYTES>>>(Hp, nullptr, Wpp, nullptr, out_p,
        PRED_NUM, PRED_PAD, HIDDEN, gt_s, gt_o, so2p, sof);
}

// round 4
// speedup vs baseline: 2.3255x; 1.2258x over previous
#include <cuda_runtime.h>
#include <cuda_bf16.h>
#include <math.h>
#include <stdint.h>

#define BQ        16384
#define OBJ_FEAT  1024
#define PVF_DIM   1024
#define PPF_DIM   64
#define HIDDEN    512
#define OBJ_NUM   1001
#define PRED_NUM  132

#define OBJ_PAD   1024
#define PRED_PAD  256

// ---------------- scratch (__device__ globals; allocation-free rule) --------
__device__ float g_Hs[(size_t)BQ * HIDDEN];
__device__ float g_Ho[(size_t)BQ * HIDDEN];
__device__ float g_Hv[(size_t)BQ * HIDDEN];
__device__ float g_Hp[(size_t)BQ * HIDDEN];
__device__ float g_Wt1[(size_t)HIDDEN * OBJ_FEAT];            // [512][1024]
__device__ float g_Wtv[(size_t)HIDDEN * PVF_DIM];             // [512][1024]
__device__ float g_Wtf[(size_t)HIDDEN * (HIDDEN + PPF_DIM)];  // [512][576]
__device__ float g_Wt2[(size_t)OBJ_PAD * HIDDEN];             // [1024][512]
__device__ float g_Wtp[(size_t)PRED_PAD * HIDDEN];            // [256][512]

// ---------------- PTX helpers ----------------
__device__ __forceinline__ uint32_t smem_u32(const void* p) {
    uint32_t a;
    asm("{ .reg .u64 t; cvta.to.shared.u64 t, %1; cvt.u32.u64 %0, t; }" : "=r"(a) : "l"(p));
    return a;
}
__device__ __forceinline__ uint32_t cvt_tf32(uint32_t raw) {
    uint32_t u;
    asm("cvt.rna.tf32.f32 %0, %1;" : "=r"(u) : "f"(__uint_as_float(raw)));
    return u;
}
__device__ __forceinline__ void mma_tf32(float* c, const uint32_t* a, const uint32_t* b) {
    asm volatile(
        "mma.sync.aligned.m16n8k8.row.col.f32.tf32.tf32.f32 "
        "{%0,%1,%2,%3}, {%4,%5,%6,%7}, {%8,%9}, {%0,%1,%2,%3};"
        : "+f"(c[0]), "+f"(c[1]), "+f"(c[2]), "+f"(c[3])
        : "r"(a[0]), "r"(a[1]), "r"(a[2]), "r"(a[3]), "r"(b[0]), "r"(b[1]));
}
#define LDSM_X4(r0, r1, r2, r3, addr) \
    asm volatile("ldmatrix.sync.aligned.m8n8.x4.shared.b16 {%0,%1,%2,%3}, [%4];" \
        : "=r"(r0), "=r"(r1), "=r"(r2), "=r"(r3) : "r"(addr))
__device__ __forceinline__ void cp16(uint32_t dst, const float* src) {
    asm volatile("cp.async.cg.shared.global [%0], [%1], 16;" :: "r"(dst), "l"(src));
}
#define CP_COMMIT() asm volatile("cp.async.commit_group;" ::: "memory")
#define CP_WAIT(n)  asm volatile("cp.async.wait_group %0;" :: "n"(n) : "memory")

// ---------------- smem layout: 3 stages, A/B tiles both [128 rows][32+4] ----
#define PITCH     36
#define T_STAGE   (128 * PITCH * 4)            // 18432 B
#define STAGE_B   (2 * T_STAGE)                // 36864 B (A then B)
#define NSTAGE    3
#define SMEM_BYTES (NSTAGE * STAGE_B)          // 110592 B

// ---------------- transpose+pad: W[K,N] -> Wt[Npad,K] (zero rows >= N) -----
__global__ void transposePad(const float* __restrict__ W, float* __restrict__ Wt,
                             int K, int N, int Npad) {
    __shared__ float t[32][33];
    const int bx = blockIdx.x * 32;   // n
    const int by = blockIdx.y * 32;   // k
#pragma unroll
    for (int j = 0; j < 32; j += 8) {
        const int y = by + threadIdx.y + j, x = bx + threadIdx.x;
        t[threadIdx.y + j][threadIdx.x] =
            (x < N && y < K) ? W[(size_t)y * N + x] : 0.0f;
    }
    __syncthreads();
#pragma unroll
    for (int j = 0; j < 32; j += 8) {
        const int row = bx + threadIdx.y + j, col = by + threadIdx.x;
        if (row < Npad && col < K)
            Wt[(size_t)row * K + col] = t[threadIdx.x][threadIdx.y + j];
    }
}

// ---------------- tf32 mma.sync GEMM, ldmatrix fragments, 3-stage ring -----
// C[M,N] = epi(A[M,K] @ Bt[N,K]^T), z-fused over gridDim.z.
// EPI 0: none | 1: +bias, ReLU | 2: + so2p[gather(gt_s,gt_o)] * exp(f)
template <int EPI, bool CONCAT>
__global__ void __launch_bounds__(256, 2)
mmagemm(const float* __restrict__ Az0, const float* __restrict__ Az1,
        const float* __restrict__ Az2, const float* __restrict__ A2,
        const float* __restrict__ Bt01, const float* __restrict__ Bt2,
        const float* __restrict__ bias01, const float* __restrict__ bias2,
        float* __restrict__ Cz0, float* __restrict__ Cz1, float* __restrict__ Cz2,
        int N, int K,
        const int* __restrict__ gts, const int* __restrict__ gto,
        const float* __restrict__ so2p, const float* __restrict__ sof)
{
    extern __shared__ __align__(16) char smem[];
    const uint32_t sbase = smem_u32(smem);

    const int z = blockIdx.z;
    const float* A    = (z == 0) ? Az0 : (z == 1) ? Az1 : Az2;
    const float* Bt   = (z == 2) ? Bt2 : Bt01;
    const float* bias = (z == 2) ? bias2 : bias01;
    float*       C    = (z == 0) ? Cz0 : (z == 1) ? Cz1 : Cz2;

    const int tid  = threadIdx.x;
    const int wid  = tid >> 5, lane = tid & 31;
    const int grp  = lane >> 2, t4 = lane & 3;
    const int wy   = wid >> 2, wx = wid & 3;      // warp grid 2x4
    const int m0   = blockIdx.y * 128;
    const int n0   = blockIdx.x * 128;
    const int mW   = wy * 64, nW = wx * 32;

    // ldmatrix per-thread address offsets (floats)
    const int lm  = lane >> 3;                    // matrix id 0..3
    const int lr8 = lane & 7;
    const int offA = ((lm & 1) * 8 + lr8) * PITCH + (lm >> 1) * 4;
    const int offB = ((lm >> 1) * 8 + lr8) * PITCH + (lm & 1) * 4;

    float acc[4][4][4];
#pragma unroll
    for (int i = 0; i < 4; i++)
#pragma unroll
        for (int j = 0; j < 4; j++)
#pragma unroll
            for (int r = 0; r < 4; r++) acc[i][j][r] = 0.0f;

    // -------- async loaders: both tiles [128 rows][32 floats], 4 f4/thread --
    const int ldRow = tid >> 1;                   // 128 rows, 2 threads/row
    const int ldQ0  = (tid & 1) * 4;              // float4 index 0..7

    auto load_stage = [&](int kc, int s) {
        const uint32_t abase = sbase + s * STAGE_B;
        const uint32_t bbase = abase + T_STAGE;
#pragma unroll
        for (int i = 0; i < 4; i++) {
            const int q = ldQ0 + i;
            const int k = kc + q * 4;
            const uint32_t dst = abase + (uint32_t)(ldRow * PITCH + q * 4) * 4u;
            const float* src;
            if (CONCAT)
                src = (k < HIDDEN) ? (A  + (size_t)(m0 + ldRow) * HIDDEN + k)
                                   : (A2 + (size_t)(m0 + ldRow) * PPF_DIM + (k - HIDDEN));
            else
                src = A + (size_t)(m0 + ldRow) * K + k;
            cp16(dst, src);
        }
#pragma unroll
        for (int i = 0; i < 4; i++) {
            const int q = ldQ0 + i;
            const uint32_t dst = bbase + (uint32_t)(ldRow * PITCH + q * 4) * 4u;
            cp16(dst, Bt + (size_t)(n0 + ldRow) * K + kc + q * 4);
        }
    };

    const int NT = K >> 5;

    load_stage(0, 0); CP_COMMIT();
    load_stage(32, 1); CP_COMMIT();

    for (int t = 0; t < NT; t++) {
        if (t + 1 < NT) { CP_WAIT(1); } else { CP_WAIT(0); }
        __syncthreads();
        if (t + 2 < NT) { load_stage((t + 2) << 5, (t + 2) % NSTAGE); CP_COMMIT(); }

        const int s = t % NSTAGE;
        const uint32_t abase = sbase + s * STAGE_B;
        const uint32_t bbase = abase + T_STAGE;
#pragma unroll
        for (int ks = 0; ks < 4; ks++) {
            const int k8 = ks * 8;
            uint32_t af[4][4], bf[4][2];
#pragma unroll
            for (int i = 0; i < 4; i++) {
                const uint32_t ad = abase + (uint32_t)((mW + i * 16) * PITCH + k8 + offA) * 4u;
                LDSM_X4(af[i][0], af[i][1], af[i][2], af[i][3], ad);
            }
#pragma unroll
            for (int jp = 0; jp < 2; jp++) {
                const uint32_t bd = bbase + (uint32_t)((nW + jp * 16) * PITCH + k8 + offB) * 4u;
                LDSM_X4(bf[2 * jp][0], bf[2 * jp][1], bf[2 * jp + 1][0], bf[2 * jp + 1][1], bd);
            }
#pragma unroll
            for (int i = 0; i < 4; i++)
#pragma unroll
                for (int r = 0; r < 4; r++) af[i][r] = cvt_tf32(af[i][r]);
#pragma unroll
            for (int j = 0; j < 4; j++) {
                bf[j][0] = cvt_tf32(bf[j][0]);
                bf[j][1] = cvt_tf32(bf[j][1]);
            }
#pragma unroll
            for (int i = 0; i < 4; i++)
#pragma unroll
                for (int j = 0; j < 4; j++)
                    mma_tf32(acc[i][j], af[i], bf[j]);
        }
    }

    // -------- epilogue --------
    float ef = 0.0f;
    if (EPI == 2) ef = expf(sof[0]);

#pragma unroll
    for (int i = 0; i < 4; i++) {
#pragma unroll
        for (int half = 0; half < 2; half++) {
            const int gm = m0 + mW + i * 16 + grp + half * 8;
            size_t sob = 0;
            if (EPI == 2)
                sob = ((size_t)gts[gm] * OBJ_NUM + (size_t)gto[gm]) * (size_t)PRED_NUM;
            float* crow = C + (size_t)gm * N;
#pragma unroll
            for (int j = 0; j < 4; j++) {
                const int gn = n0 + nW + j * 8 + t4 * 2;
#pragma unroll
                for (int e = 0; e < 2; e++) {
                    const int col = gn + e;
                    const float a = acc[i][j][half * 2 + e];
                    if (EPI == 1) {
                        crow[col] = fmaxf(a + bias[col], 0.0f);
                    } else if (EPI == 2) {
                        if (col < N) crow[col] = a + so2p[sob + col] * ef;
                    } else {
                        if (col < N) crow[col] = a;
                    }
                }
            }
        }
    }
}

// ---------------- host ----------------
extern "C" void kernel_launch(void* const* d_in, const int* in_sizes, int n_in,
                              void* d_out, int out_size)
{
    const float* inp_sf  = (const float*)d_in[0];
    const float* inp_of  = (const float*)d_in[1];
    const float* inp_ppf = (const float*)d_in[2];
    const float* inp_pvf = (const float*)d_in[3];
    const int*   gt_s    = (const int*)d_in[4];
    const int*   gt_o    = (const int*)d_in[5];
    const float* W_obj1  = (const float*)d_in[6];
    const float* b_obj1  = (const float*)d_in[7];
    const float* W_obj2  = (const float*)d_in[8];
    const float* W_pvf   = (const float*)d_in[9];
    const float* b_pvf   = (const float*)d_in[10];
    const float* W_pf    = (const float*)d_in[11];
    const float* b_pf    = (const float*)d_in[12];
    const float* W_pred  = (const float*)d_in[13];
    const float* so2p    = (const float*)d_in[14];
    const float* sof     = (const float*)d_in[15];

    float* out   = (float*)d_out;
    float* out_s = out;
    float* out_o = out + (size_t)BQ * OBJ_NUM;
    float* out_p = out + (size_t)2 * BQ * OBJ_NUM;

    float *Hs, *Ho, *Hv, *Hp, *Wt1, *Wtv, *Wtf, *Wt2, *Wtp;
    cudaGetSymbolAddress((void**)&Hs,  g_Hs);
    cudaGetSymbolAddress((void**)&Ho,  g_Ho);
    cudaGetSymbolAddress((void**)&Hv,  g_Hv);
    cudaGetSymbolAddress((void**)&Hp,  g_Hp);
    cudaGetSymbolAddress((void**)&Wt1, g_Wt1);
    cudaGetSymbolAddress((void**)&Wtv, g_Wtv);
    cudaGetSymbolAddress((void**)&Wtf, g_Wtf);
    cudaGetSymbolAddress((void**)&Wt2, g_Wt2);
    cudaGetSymbolAddress((void**)&Wtp, g_Wtp);

    cudaFuncSetAttribute(mmagemm<1, false>, cudaFuncAttributeMaxDynamicSharedMemorySize, SMEM_BYTES);
    cudaFuncSetAttribute(mmagemm<1, true>,  cudaFuncAttributeMaxDynamicSharedMemorySize, SMEM_BYTES);
    cudaFuncSetAttribute(mmagemm<0, false>, cudaFuncAttributeMaxDynamicSharedMemorySize, SMEM_BYTES);
    cudaFuncSetAttribute(mmagemm<2, false>, cudaFuncAttributeMaxDynamicSharedMemorySize, SMEM_BYTES);

    const dim3 tb(32, 8);
    transposePad<<<dim3(16, 32), tb>>>(W_obj1, Wt1, OBJ_FEAT, HIDDEN, HIDDEN);
    transposePad<<<dim3(16, 32), tb>>>(W_pvf,  Wtv, PVF_DIM,  HIDDEN, HIDDEN);
    transposePad<<<dim3(16, 18), tb>>>(W_pf,   Wtf, HIDDEN + PPF_DIM, HIDDEN, HIDDEN);
    transposePad<<<dim3(32, 16), tb>>>(W_obj2, Wt2, HIDDEN, OBJ_NUM,  OBJ_PAD);
    transposePad<<<dim3(8, 16), tb>>>(W_pred,  Wtp, HIDDEN, PRED_NUM, PRED_PAD);

    const dim3 blk(256);

    // stage 1: sf/of/pvf fused over z
    mmagemm<1, false><<<dim3(HIDDEN / 128, BQ / 128, 3), blk, SMEM_BYTES>>>(
        inp_sf, inp_of, inp_pvf, nullptr, Wt1, Wtv, b_obj1, b_pvf,
        Hs, Ho, Hv, HIDDEN, OBJ_FEAT, nullptr, nullptr, nullptr, nullptr);

    // stage 2: pf_emb (concat Hv | ppf), K = 576
    mmagemm<1, true><<<dim3(HIDDEN / 128, BQ / 128, 1), blk, SMEM_BYTES>>>(
        Hv, Hv, Hv, inp_ppf, Wtf, Wtf, b_pf, b_pf,
        Hp, Hp, Hp, HIDDEN, HIDDEN + PPF_DIM, nullptr, nullptr, nullptr, nullptr);

    // stage 3a: s/o scores fused over z
    mmagemm<0, false><<<dim3(OBJ_PAD / 128, BQ / 128, 2), blk, SMEM_BYTES>>>(
        Hs, Ho, Ho, nullptr, Wt2, Wt2, nullptr, nullptr,
        out_s, out_o, out_o, OBJ_NUM, HIDDEN, nullptr, nullptr, nullptr, nullptr);

    // stage 3b: predicate scores + so2p gather
    mmagemm<2, false><<<dim3(PRED_PAD / 128, BQ / 128, 1), blk, SMEM_BYTES>>>(
        Hp, Hp, Hp, nullptr, Wtp, Wtp, nullptr, nullptr,
        out_p, out_p, out_p, PRED_NUM, HIDDEN, gt_s, gt_o, so2p, sof);
}

// round 5
// speedup vs baseline: 4.3088x; 1.8529x over previous
#include <cuda_runtime.h>
#include <cuda_fp16.h>
#include <math.h>
#include <stdint.h>

#define BQ        16384
#define OBJ_FEAT  1024
#define PVF_DIM   1024
#define PPF_DIM   64
#define HIDDEN    512
#define OBJ_NUM   1001
#define PRED_NUM  132

#define OBJ_PAD   1024
#define PRED_PAD  256

// ---------------- scratch (__device__ globals; allocation-free rule) --------
__device__ __half g_sfh[(size_t)BQ * OBJ_FEAT];
__device__ __half g_ofh[(size_t)BQ * OBJ_FEAT];
__device__ __half g_pvfh[(size_t)BQ * PVF_DIM];
__device__ __half g_ppfh[(size_t)BQ * PPF_DIM];
__device__ __half g_Hs[(size_t)BQ * HIDDEN];
__device__ __half g_Ho[(size_t)BQ * HIDDEN];
__device__ __half g_Hv[(size_t)BQ * HIDDEN];
__device__ __half g_Hp[(size_t)BQ * HIDDEN];
__device__ __half g_Wt1[(size_t)HIDDEN * OBJ_FEAT];            // [512][1024]
__device__ __half g_Wtv[(size_t)HIDDEN * PVF_DIM];             // [512][1024]
__device__ __half g_Wtf[(size_t)HIDDEN * (HIDDEN + PPF_DIM)];  // [512][576]
__device__ __half g_Wt2[(size_t)OBJ_PAD * HIDDEN];             // [1024][512]
__device__ __half g_Wtp[(size_t)PRED_PAD * HIDDEN];            // [256][512]

// ---------------- PTX helpers ----------------
__device__ __forceinline__ uint32_t smem_u32(const void* p) {
    uint32_t a;
    asm("{ .reg .u64 t; cvta.to.shared.u64 t, %1; cvt.u32.u64 %0, t; }" : "=r"(a) : "l"(p));
    return a;
}
__device__ __forceinline__ void mma_f16(float* c, const uint32_t* a, const uint32_t* b) {
    asm volatile(
        "mma.sync.aligned.m16n8k16.row.col.f32.f16.f16.f32 "
        "{%0,%1,%2,%3}, {%4,%5,%6,%7}, {%8,%9}, {%0,%1,%2,%3};"
        : "+f"(c[0]), "+f"(c[1]), "+f"(c[2]), "+f"(c[3])
        : "r"(a[0]), "r"(a[1]), "r"(a[2]), "r"(a[3]), "r"(b[0]), "r"(b[1]));
}
#define LDSM_X4(r0, r1, r2, r3, addr) \
    asm volatile("ldmatrix.sync.aligned.m8n8.x4.shared.b16 {%0,%1,%2,%3}, [%4];" \
        : "=r"(r0), "=r"(r1), "=r"(r2), "=r"(r3) : "r"(addr))
__device__ __forceinline__ void cp16(uint32_t dst, const void* src) {
    asm volatile("cp.async.cg.shared.global [%0], [%1], 16;" :: "r"(dst), "l"(src));
}
#define CP_COMMIT() asm volatile("cp.async.commit_group;" ::: "memory")
#define CP_WAIT(n)  asm volatile("cp.async.wait_group %0;" :: "n"(n) : "memory")

// ---------------- smem layout: 3 stages, A/B tiles [128 rows][64+8 halves] --
#define ROWB      144                           // 128B data + 16B pad
#define T_STAGE   (128 * ROWB)                  // 18432 B
#define STAGE_B   (2 * T_STAGE)                 // 36864 B (A then B)
#define NSTAGE    3
#define SMEM_BYTES (NSTAGE * STAGE_B)           // 110592 B

// ---------------- fp32 -> fp16 conversion (8 elems/thread) ----------------
__global__ void f2h3(const float* __restrict__ i0, const float* __restrict__ i1,
                     const float* __restrict__ i2,
                     __half* __restrict__ o0, __half* __restrict__ o1,
                     __half* __restrict__ o2, int n8) {
    const float* in = (blockIdx.z == 0) ? i0 : (blockIdx.z == 1) ? i1 : i2;
    __half* out = (blockIdx.z == 0) ? o0 : (blockIdx.z == 1) ? o1 : o2;
    int i = blockIdx.x * blockDim.x + threadIdx.x;
    if (i < n8) {
        const float4 a = *reinterpret_cast<const float4*>(in + i * 8);
        const float4 b = *reinterpret_cast<const float4*>(in + i * 8 + 4);
        __half2 h[4];
        h[0] = __floats2half2_rn(a.x, a.y);
        h[1] = __floats2half2_rn(a.z, a.w);
        h[2] = __floats2half2_rn(b.x, b.y);
        h[3] = __floats2half2_rn(b.z, b.w);
        *reinterpret_cast<uint4*>(out + i * 8) = *reinterpret_cast<uint4*>(h);
    }
}

// ---------------- transpose+pad+convert: W[K,N] -> Wt[Npad][K] half --------
__global__ void transposePadH(const float* __restrict__ W, __half* __restrict__ Wt,
                              int K, int N, int Npad) {
    __shared__ float t[32][33];
    const int bx = blockIdx.x * 32;   // n
    const int by = blockIdx.y * 32;   // k
#pragma unroll
    for (int j = 0; j < 32; j += 8) {
        const int y = by + threadIdx.y + j, x = bx + threadIdx.x;
        t[threadIdx.y + j][threadIdx.x] =
            (x < N && y < K) ? W[(size_t)y * N + x] : 0.0f;
    }
    __syncthreads();
#pragma unroll
    for (int j = 0; j < 32; j += 8) {
        const int row = bx + threadIdx.y + j, col = by + threadIdx.x;
        if (row < Npad && col < K)
            Wt[(size_t)row * K + col] = __float2half(t[threadIdx.x][threadIdx.y + j]);
    }
}

// ---------------- fp16 mma.sync GEMM, ldmatrix, 3-stage ring, K-chunk 64 ---
// C[M,N] = epi(A[M,K] @ Bt[N,K]^T), z-fused.
// EPI 0: none | 1: +bias, ReLU | 2: + so2p[gather]*exp(f).  OUTH: C is half.
template <int EPI, bool CONCAT, bool OUTH>
__global__ void __launch_bounds__(256, 2)
mmagemm(const __half* __restrict__ Az0, const __half* __restrict__ Az1,
        const __half* __restrict__ Az2, const __half* __restrict__ A2,
        const __half* __restrict__ Bt01, const __half* __restrict__ Bt2,
        const float* __restrict__ bias01, const float* __restrict__ bias2,
        void* __restrict__ Cz0, void* __restrict__ Cz1, void* __restrict__ Cz2,
        int N, int K,
        const int* __restrict__ gts, const int* __restrict__ gto,
        const float* __restrict__ so2p, const float* __restrict__ sof)
{
    extern __shared__ __align__(16) char smem[];
    const uint32_t sbase = smem_u32(smem);

    const int z = blockIdx.z;
    const __half* A   = (z == 0) ? Az0 : (z == 1) ? Az1 : Az2;
    const __half* Bt  = (z == 2) ? Bt2 : Bt01;
    const float* bias = (z == 2) ? bias2 : bias01;
    void* Cv          = (z == 0) ? Cz0 : (z == 1) ? Cz1 : Cz2;

    const int tid  = threadIdx.x;
    const int wid  = tid >> 5, lane = tid & 31;
    const int grp  = lane >> 2, t4 = lane & 3;
    const int wy   = wid >> 2, wx = wid & 3;      // warp grid 2x4
    const int m0   = blockIdx.y * 128;
    const int n0   = blockIdx.x * 128;
    const int mW   = wy * 64, nW = wx * 32;

    // ldmatrix per-thread base offsets (bytes within tile)
    const uint32_t offA = (uint32_t)(lane & 15) * ROWB + (uint32_t)(lane >> 4) * 16;
    const uint32_t bRow = (uint32_t)((lane & 7) + ((lane >> 4) & 1) * 8);
    const uint32_t offB = bRow * ROWB + (uint32_t)((lane >> 3) & 1) * 16;

    float acc[4][4][4];
#pragma unroll
    for (int i = 0; i < 4; i++)
#pragma unroll
        for (int j = 0; j < 4; j++)
#pragma unroll
            for (int r = 0; r < 4; r++) acc[i][j][r] = 0.0f;

    // -------- async loaders: [128 rows][64 halves], 4 x 16B per thread/tile -
    const int ldRow = tid >> 1;                   // 128 rows, 2 threads/row
    const int ldQ0  = (tid & 1) * 4;              // 16B-chunk index 0..7

    auto load_stage = [&](int kc, int s) {
        const uint32_t abase = sbase + s * STAGE_B;
        const uint32_t bbase = abase + T_STAGE;
#pragma unroll
        for (int i = 0; i < 4; i++) {
            const int q = ldQ0 + i;
            const int k = kc + q * 8;
            const uint32_t dst = abase + (uint32_t)ldRow * ROWB + (uint32_t)q * 16;
            const __half* src;
            if (CONCAT)
                src = (k < HIDDEN) ? (A  + (size_t)(m0 + ldRow) * HIDDEN + k)
                                   : (A2 + (size_t)(m0 + ldRow) * PPF_DIM + (k - HIDDEN));
            else
                src = A + (size_t)(m0 + ldRow) * K + k;
            cp16(dst, src);
        }
#pragma unroll
        for (int i = 0; i < 4; i++) {
            const int q = ldQ0 + i;
            const uint32_t dst = bbase + (uint32_t)ldRow * ROWB + (uint32_t)q * 16;
            cp16(dst, Bt + (size_t)(n0 + ldRow) * K + kc + q * 8);
        }
    };

    const int NT = K >> 6;                        // K-chunk = 64

    load_stage(0, 0); CP_COMMIT();
    load_stage(64, 1); CP_COMMIT();

    for (int t = 0; t < NT; t++) {
        if (t + 1 < NT) { CP_WAIT(1); } else { CP_WAIT(0); }
        __syncthreads();
        if (t + 2 < NT) { load_stage((t + 2) << 6, (t + 2) % NSTAGE); CP_COMMIT(); }

        const int s = t % NSTAGE;
        const uint32_t abase = sbase + s * STAGE_B;
        const uint32_t bbase = abase + T_STAGE;
#pragma unroll
        for (int ks = 0; ks < 4; ks++) {          // 4 k16-steps per chunk
            const uint32_t kb = (uint32_t)ks * 32;  // 16 halves = 32B
            uint32_t af[4][4], bf[4][2];
#pragma unroll
            for (int i = 0; i < 4; i++) {
                const uint32_t ad = abase + (uint32_t)(mW + i * 16) * ROWB + kb + offA;
                LDSM_X4(af[i][0], af[i][1], af[i][2], af[i][3], ad);
            }
#pragma unroll
            for (int jp = 0; jp < 2; jp++) {
                const uint32_t bd = bbase + (uint32_t)(nW + jp * 16) * ROWB + kb + offB;
                LDSM_X4(bf[2 * jp][0], bf[2 * jp][1], bf[2 * jp + 1][0], bf[2 * jp + 1][1], bd);
            }
#pragma unroll
            for (int i = 0; i < 4; i++)
#pragma unroll
                for (int j = 0; j < 4; j++)
                    mma_f16(acc[i][j], af[i], bf[j]);
        }
    }

    // -------- epilogue --------
    float ef = 0.0f;
    if (EPI == 2) ef = expf(sof[0]);

#pragma unroll
    for (int i = 0; i < 4; i++) {
#pragma unroll
        for (int half = 0; half < 2; half++) {
            const int gm = m0 + mW + i * 16 + grp + half * 8;
            size_t sob = 0;
            if (EPI == 2)
                sob = ((size_t)gts[gm] * OBJ_NUM + (size_t)gto[gm]) * (size_t)PRED_NUM;
#pragma unroll
            for (int j = 0; j < 4; j++) {
                const int gn = n0 + nW + j * 8 + t4 * 2;
                const float v0 = acc[i][j][half * 2 + 0];
                const float v1 = acc[i][j][half * 2 + 1];
                if (OUTH) {
                    __half* crow = (__half*)Cv + (size_t)gm * N;
                    float a0 = v0, a1 = v1;
                    if (EPI == 1) {
                        a0 = fmaxf(a0 + bias[gn], 0.0f);
                        a1 = fmaxf(a1 + bias[gn + 1], 0.0f);
                    }
                    *reinterpret_cast<__half2*>(crow + gn) = __floats2half2_rn(a0, a1);
                } else {
                    float* crow = (float*)Cv + (size_t)gm * N;
                    if (EPI == 2) {
                        if (gn < N)     crow[gn]     = v0 + so2p[sob + gn] * ef;
                        if (gn + 1 < N) crow[gn + 1] = v1 + so2p[sob + gn + 1] * ef;
                    } else {
                        if (gn < N)     crow[gn]     = v0;
                        if (gn + 1 < N) crow[gn + 1] = v1;
                    }
                }
            }
        }
    }
}

// ---------------- host ----------------
extern "C" void kernel_launch(void* const* d_in, const int* in_sizes, int n_in,
                              void* d_out, int out_size)
{
    const float* inp_sf  = (const float*)d_in[0];
    const float* inp_of  = (const float*)d_in[1];
    const float* inp_ppf = (const float*)d_in[2];
    const float* inp_pvf = (const float*)d_in[3];
    const int*   gt_s    = (const int*)d_in[4];
    const int*   gt_o    = (const int*)d_in[5];
    const float* W_obj1  = (const float*)d_in[6];
    const float* b_obj1  = (const float*)d_in[7];
    const float* W_obj2  = (const float*)d_in[8];
    const float* W_pvf   = (const float*)d_in[9];
    const float* b_pvf   = (const float*)d_in[10];
    const float* W_pf    = (const float*)d_in[11];
    const float* b_pf    = (const float*)d_in[12];
    const float* W_pred  = (const float*)d_in[13];
    const float* so2p    = (const float*)d_in[14];
    const float* sof     = (const float*)d_in[15];

    float* out   = (float*)d_out;
    float* out_s = out;
    float* out_o = out + (size_t)BQ * OBJ_NUM;
    float* out_p = out + (size_t)2 * BQ * OBJ_NUM;

    __half *sfh, *ofh, *pvfh, *ppfh, *Hs, *Ho, *Hv, *Hp, *Wt1, *Wtv, *Wtf, *Wt2, *Wtp;
    cudaGetSymbolAddress((void**)&sfh,  g_sfh);
    cudaGetSymbolAddress((void**)&ofh,  g_ofh);
    cudaGetSymbolAddress((void**)&pvfh, g_pvfh);
    cudaGetSymbolAddress((void**)&ppfh, g_ppfh);
    cudaGetSymbolAddress((void**)&Hs,  g_Hs);
    cudaGetSymbolAddress((void**)&Ho,  g_Ho);
    cudaGetSymbolAddress((void**)&Hv,  g_Hv);
    cudaGetSymbolAddress((void**)&Hp,  g_Hp);
    cudaGetSymbolAddress((void**)&Wt1, g_Wt1);
    cudaGetSymbolAddress((void**)&Wtv, g_Wtv);
    cudaGetSymbolAddress((void**)&Wtf, g_Wtf);
    cudaGetSymbolAddress((void**)&Wt2, g_Wt2);
    cudaGetSymbolAddress((void**)&Wtp, g_Wtp);

    cudaFuncSetAttribute(mmagemm<1, false, true>,  cudaFuncAttributeMaxDynamicSharedMemorySize, SMEM_BYTES);
    cudaFuncSetAttribute(mmagemm<1, true,  true>,  cudaFuncAttributeMaxDynamicSharedMemorySize, SMEM_BYTES);
    cudaFuncSetAttribute(mmagemm<0, false, false>, cudaFuncAttributeMaxDynamicSharedMemorySize, SMEM_BYTES);
    cudaFuncSetAttribute(mmagemm<2, false, false>, cudaFuncAttributeMaxDynamicSharedMemorySize, SMEM_BYTES);

    // input conversions
    {
        const int n8 = BQ * OBJ_FEAT / 8;
        f2h3<<<dim3((n8 + 255) / 256, 1, 3), 256>>>(inp_sf, inp_of, inp_pvf,
                                                    sfh, ofh, pvfh, n8);
        const int p8 = BQ * PPF_DIM / 8;
        f2h3<<<dim3((p8 + 255) / 256, 1, 1), 256>>>(inp_ppf, inp_ppf, inp_ppf,
                                                    ppfh, ppfh, ppfh, p8);
    }

    // weight transpose+pad+convert
    const dim3 tb(32, 8);
    transposePadH<<<dim3(16, 32), tb>>>(W_obj1, Wt1, OBJ_FEAT, HIDDEN, HIDDEN);
    transposePadH<<<dim3(16, 32), tb>>>(W_pvf,  Wtv, PVF_DIM,  HIDDEN, HIDDEN);
    transposePadH<<<dim3(16, 18), tb>>>(W_pf,   Wtf, HIDDEN + PPF_DIM, HIDDEN, HIDDEN);
    transposePadH<<<dim3(32, 16), tb>>>(W_obj2, Wt2, HIDDEN, OBJ_NUM,  OBJ_PAD);
    transposePadH<<<dim3(8, 16), tb>>>(W_pred,  Wtp, HIDDEN, PRED_NUM, PRED_PAD);

    const dim3 blk(256);

    // stage 1: sf/of/pvf fused over z (K=1024, N=512)
    mmagemm<1, false, true><<<dim3(HIDDEN / 128, BQ / 128, 3), blk, SMEM_BYTES>>>(
        sfh, ofh, pvfh, nullptr, Wt1, Wtv, b_obj1, b_pvf,
        Hs, Ho, Hv, HIDDEN, OBJ_FEAT, nullptr, nullptr, nullptr, nullptr);

    // stage 2: pf_emb (concat Hv | ppf), K = 576
    mmagemm<1, true, true><<<dim3(HIDDEN / 128, BQ / 128, 1), blk, SMEM_BYTES>>>(
        Hv, Hv, Hv, ppfh, Wtf, Wtf, b_pf, b_pf,
        Hp, Hp, Hp, HIDDEN, HIDDEN + PPF_DIM, nullptr, nullptr, nullptr, nullptr);

    // stage 3a: s/o scores fused over z (K=512, N=1001 padded 1024)
    mmagemm<0, false, false><<<dim3(OBJ_PAD / 128, BQ / 128, 2), blk, SMEM_BYTES>>>(
        Hs, Ho, Ho, nullptr, Wt2, Wt2, nullptr, nullptr,
        out_s, out_o, out_o, OBJ_NUM, HIDDEN, nullptr, nullptr, nullptr, nullptr);

    // stage 3b: predicate scores + so2p gather (K=512, N=132 padded 256)
    mmagemm<2, false, false><<<dim3(PRED_PAD / 128, BQ / 128, 1), blk, SMEM_BYTES>>>(
        Hp, Hp, Hp, nullptr, Wtp, Wtp, nullptr, nullptr,
        out_p, out_p, out_p, PRED_NUM, HIDDEN, gt_s, gt_o, so2p, sof);
}

// round 6
// speedup vs baseline: 4.5303x; 1.0514x over previous
#include <cuda_runtime.h>
#include <cuda_fp16.h>
#include <math.h>
#include <stdint.h>

#define BQ        16384
#define OBJ_FEAT  1024
#define PVF_DIM   1024
#define PPF_DIM   64
#define HIDDEN    512
#define OBJ_NUM   1001
#define PRED_NUM  132

#define OBJ_PAD   1024
#define PRED_PAD  256

// ---------------- scratch (__device__ globals; allocation-free rule) --------
__device__ __half g_sfh[(size_t)BQ * OBJ_FEAT];
__device__ __half g_ofh[(size_t)BQ * OBJ_FEAT];
__device__ __half g_pvfh[(size_t)BQ * PVF_DIM];
__device__ __half g_ppfh[(size_t)BQ * PPF_DIM];
__device__ __half g_Hs[(size_t)BQ * HIDDEN];
__device__ __half g_Ho[(size_t)BQ * HIDDEN];
__device__ __half g_Hv[(size_t)BQ * HIDDEN];
__device__ __half g_Hp[(size_t)BQ * HIDDEN];
__device__ __half g_Wt1[(size_t)HIDDEN * OBJ_FEAT];            // [512][1024]
__device__ __half g_Wtv[(size_t)HIDDEN * PVF_DIM];             // [512][1024]
__device__ __half g_Wtf[(size_t)HIDDEN * (HIDDEN + PPF_DIM)];  // [512][576]
__device__ __half g_Wt2[(size_t)OBJ_PAD * HIDDEN];             // [1024][512]
__device__ __half g_Wtp[(size_t)PRED_PAD * HIDDEN];            // [256][512]

// ---------------- PTX helpers ----------------
__device__ __forceinline__ uint32_t smem_u32(const void* p) {
    uint32_t a;
    asm("{ .reg .u64 t; cvta.to.shared.u64 t, %1; cvt.u32.u64 %0, t; }" : "=r"(a) : "l"(p));
    return a;
}
__device__ __forceinline__ void mma_f16(float* c, const uint32_t* a, const uint32_t* b) {
    asm volatile(
        "mma.sync.aligned.m16n8k16.row.col.f32.f16.f16.f32 "
        "{%0,%1,%2,%3}, {%4,%5,%6,%7}, {%8,%9}, {%0,%1,%2,%3};"
        : "+f"(c[0]), "+f"(c[1]), "+f"(c[2]), "+f"(c[3])
        : "r"(a[0]), "r"(a[1]), "r"(a[2]), "r"(a[3]), "r"(b[0]), "r"(b[1]));
}
#define LDSM_X4(r0, r1, r2, r3, addr) \
    asm volatile("ldmatrix.sync.aligned.m8n8.x4.shared.b16 {%0,%1,%2,%3}, [%4];" \
        : "=r"(r0), "=r"(r1), "=r"(r2), "=r"(r3) : "r"(addr))
__device__ __forceinline__ void cp16cg(uint32_t dst, const void* src) {
    asm volatile("cp.async.cg.shared.global [%0], [%1], 16;" :: "r"(dst), "l"(src));
}
__device__ __forceinline__ void cp16ca(uint32_t dst, const void* src) {
    asm volatile("cp.async.ca.shared.global [%0], [%1], 16;" :: "r"(dst), "l"(src));
}
#define CP_COMMIT() asm volatile("cp.async.commit_group;" ::: "memory")
#define CP_WAIT(n)  asm volatile("cp.async.wait_group %0;" :: "n"(n) : "memory")

// ---------------- smem layout: 3 stages, A/B tiles [128 rows][64+8 halves] --
#define ROWB      144                           // 128B data + 16B pad
#define T_STAGE   (128 * ROWB)                  // 18432 B
#define STAGE_B   (2 * T_STAGE)                 // 36864 B (A then B)
#define NSTAGE    3
#define SMEM_BYTES (NSTAGE * STAGE_B)           // 110592 B

// ---------------- fused prep: conversions (z 0-3) + transposes (z 4-8) -----
__global__ void prep(const float* __restrict__ sf, const float* __restrict__ of,
                     const float* __restrict__ pvf, const float* __restrict__ ppf,
                     __half* __restrict__ sfh, __half* __restrict__ ofh,
                     __half* __restrict__ pvfh, __half* __restrict__ ppfh,
                     const float* __restrict__ W1, const float* __restrict__ Wv,
                     const float* __restrict__ Wf, const float* __restrict__ W2,
                     const float* __restrict__ Wp,
                     __half* __restrict__ Wt1, __half* __restrict__ Wtv,
                     __half* __restrict__ Wtf, __half* __restrict__ Wt2,
                     __half* __restrict__ Wtp)
{
    const int z = blockIdx.z;
    if (z < 4) {
        const float* in = (z == 0) ? sf : (z == 1) ? of : (z == 2) ? pvf : ppf;
        __half* out = (z == 0) ? sfh : (z == 1) ? ofh : (z == 2) ? pvfh : ppfh;
        const int n8 = (z == 3) ? (BQ * PPF_DIM / 8) : (BQ * OBJ_FEAT / 8);
        for (int i = blockIdx.x * blockDim.x + threadIdx.x; i < n8;
             i += gridDim.x * blockDim.x) {
            const float4 a = *reinterpret_cast<const float4*>(in + (size_t)i * 8);
            const float4 b = *reinterpret_cast<const float4*>(in + (size_t)i * 8 + 4);
            __half2 h[4];
            h[0] = __floats2half2_rn(a.x, a.y);
            h[1] = __floats2half2_rn(a.z, a.w);
            h[2] = __floats2half2_rn(b.x, b.y);
            h[3] = __floats2half2_rn(b.z, b.w);
            *reinterpret_cast<uint4*>(out + (size_t)i * 8) = *reinterpret_cast<uint4*>(h);
        }
    } else {
        const float* W; __half* Wt; int K, N, Npad;
        switch (z) {
            case 4: W = W1; Wt = Wt1; K = OBJ_FEAT; N = HIDDEN; Npad = HIDDEN; break;
            case 5: W = Wv; Wt = Wtv; K = PVF_DIM;  N = HIDDEN; Npad = HIDDEN; break;
            case 6: W = Wf; Wt = Wtf; K = HIDDEN + PPF_DIM; N = HIDDEN; Npad = HIDDEN; break;
            case 7: W = W2; Wt = Wt2; K = HIDDEN; N = OBJ_NUM;  Npad = OBJ_PAD; break;
            default: W = Wp; Wt = Wtp; K = HIDDEN; N = PRED_NUM; Npad = PRED_PAD; break;
        }
        __shared__ float t[32][33];
        const int tx5 = threadIdx.x & 31, ty3 = threadIdx.x >> 5;  // (32, 8)
        const int ntx = Npad / 32, nty = (K + 31) / 32;
        for (int tile = blockIdx.x; tile < ntx * nty; tile += gridDim.x) {
            const int bx = (tile % ntx) * 32;   // n
            const int by = (tile / ntx) * 32;   // k
#pragma unroll
            for (int j = 0; j < 32; j += 8) {
                const int y = by + ty3 + j, x = bx + tx5;
                t[ty3 + j][tx5] = (x < N && y < K) ? W[(size_t)y * N + x] : 0.0f;
            }
            __syncthreads();
#pragma unroll
            for (int j = 0; j < 32; j += 8) {
                const int row = bx + ty3 + j, col = by + tx5;
                if (row < Npad && col < K)
                    Wt[(size_t)row * K + col] = __float2half(t[tx5][ty3 + j]);
            }
            __syncthreads();
        }
    }
}

// ---------------- fp16 mma.sync GEMM, ldmatrix, 3-stage ring, K-chunk 64 ---
// C[M,N] = epi(A[M,K] @ Bt[N,K]^T), z-fused.
// EPI 0: none | 1: +bias, ReLU | 2: + so2p[gather]*exp(f).  OUTH: C is half.
template <int EPI, bool CONCAT, bool OUTH>
__global__ void __launch_bounds__(256, 2)
mmagemm(const __half* __restrict__ Az0, const __half* __restrict__ Az1,
        const __half* __restrict__ Az2, const __half* __restrict__ A2,
        const __half* __restrict__ Bt01, const __half* __restrict__ Bt2,
        const float* __restrict__ bias01, const float* __restrict__ bias2,
        void* __restrict__ Cz0, void* __restrict__ Cz1, void* __restrict__ Cz2,
        int N, int K,
        const int* __restrict__ gts, const int* __restrict__ gto,
        const float* __restrict__ so2p, const float* __restrict__ sof)
{
    extern __shared__ __align__(16) char smem[];
    const uint32_t sbase = smem_u32(smem);

    const int z = blockIdx.z;
    const __half* A   = (z == 0) ? Az0 : (z == 1) ? Az1 : Az2;
    const __half* Bt  = (z == 2) ? Bt2 : Bt01;
    const float* bias = (z == 2) ? bias2 : bias01;
    void* Cv          = (z == 0) ? Cz0 : (z == 1) ? Cz1 : Cz2;

    const int tid  = threadIdx.x;
    const int wid  = tid >> 5, lane = tid & 31;
    const int grp  = lane >> 2, t4 = lane & 3;
    const int wy   = wid >> 2, wx = wid & 3;      // warp grid 2x4
    const int m0   = blockIdx.y * 128;
    const int n0   = blockIdx.x * 128;
    const int mW   = wy * 64, nW = wx * 32;

    // ldmatrix per-thread base offsets (bytes within tile)
    const uint32_t offA = (uint32_t)(lane & 15) * ROWB + (uint32_t)(lane >> 4) * 16;
    const uint32_t bRow = (uint32_t)((lane & 7) + ((lane >> 4) & 1) * 8);
    const uint32_t offB = bRow * ROWB + (uint32_t)((lane >> 3) & 1) * 16;

    float acc[4][4][4];
#pragma unroll
    for (int i = 0; i < 4; i++)
#pragma unroll
        for (int j = 0; j < 4; j++)
#pragma unroll
            for (int r = 0; r < 4; r++) acc[i][j][r] = 0.0f;

    // -------- async loaders: [128 rows][64 halves], 4 x 16B per thread/tile -
    const int ldRow = tid >> 1;                   // 128 rows, 2 threads/row
    const int ldQ0  = (tid & 1) * 4;              // 16B-chunk index 0..7

    auto load_stage = [&](int kc, int s) {
        const uint32_t abase = sbase + s * STAGE_B;
        const uint32_t bbase = abase + T_STAGE;
#pragma unroll
        for (int i = 0; i < 4; i++) {
            const int q = ldQ0 + i;
            const int k = kc + q * 8;
            const uint32_t dst = abase + (uint32_t)ldRow * ROWB + (uint32_t)q * 16;
            const __half* src;
            if (CONCAT)
                src = (k < HIDDEN) ? (A  + (size_t)(m0 + ldRow) * HIDDEN + k)
                                   : (A2 + (size_t)(m0 + ldRow) * PPF_DIM + (k - HIDDEN));
            else
                src = A + (size_t)(m0 + ldRow) * K + k;
            cp16cg(dst, src);
        }
#pragma unroll
        for (int i = 0; i < 4; i++) {
            const int q = ldQ0 + i;
            const uint32_t dst = bbase + (uint32_t)ldRow * ROWB + (uint32_t)q * 16;
            cp16ca(dst, Bt + (size_t)(n0 + ldRow) * K + kc + q * 8);  // weights: L1-cache
        }
    };

    const int NT = K >> 6;                        // K-chunk = 64

    load_stage(0, 0); CP_COMMIT();
    load_stage(64, 1); CP_COMMIT();

    for (int t = 0; t < NT; t++) {
        if (t + 1 < NT) { CP_WAIT(1); } else { CP_WAIT(0); }
        __syncthreads();
        if (t + 2 < NT) { load_stage((t + 2) << 6, (t + 2) % NSTAGE); CP_COMMIT(); }

        const int s = t % NSTAGE;
        const uint32_t abase = sbase + s * STAGE_B;
        const uint32_t bbase = abase + T_STAGE;
#pragma unroll
        for (int ks = 0; ks < 4; ks++) {          // 4 k16-steps per chunk
            const uint32_t kb = (uint32_t)ks * 32;  // 16 halves = 32B
            uint32_t af[4][4], bf[4][2];
#pragma unroll
            for (int i = 0; i < 4; i++) {
                const uint32_t ad = abase + (uint32_t)(mW + i * 16) * ROWB + kb + offA;
                LDSM_X4(af[i][0], af[i][1], af[i][2], af[i][3], ad);
            }
#pragma unroll
            for (int jp = 0; jp < 2; jp++) {
                const uint32_t bd = bbase + (uint32_t)(nW + jp * 16) * ROWB + kb + offB;
                LDSM_X4(bf[2 * jp][0], bf[2 * jp][1], bf[2 * jp + 1][0], bf[2 * jp + 1][1], bd);
            }
#pragma unroll
            for (int i = 0; i < 4; i++)
#pragma unroll
                for (int j = 0; j < 4; j++)
                    mma_f16(acc[i][j], af[i], bf[j]);
        }
    }

    // -------- epilogue --------
    float ef = 0.0f;
    if (EPI == 2) ef = expf(sof[0]);

#pragma unroll
    for (int i = 0; i < 4; i++) {
#pragma unroll
        for (int half = 0; half < 2; half++) {
            const int gm = m0 + mW + i * 16 + grp + half * 8;
            size_t sob = 0;
            if (EPI == 2)
                sob = ((size_t)gts[gm] * OBJ_NUM + (size_t)gto[gm]) * (size_t)PRED_NUM;
#pragma unroll
            for (int j = 0; j < 4; j++) {
                const int gn = n0 + nW + j * 8 + t4 * 2;
                const float v0 = acc[i][j][half * 2 + 0];
                const float v1 = acc[i][j][half * 2 + 1];
                if (OUTH) {
                    __half* crow = (__half*)Cv + (size_t)gm * N;
                    float a0 = v0, a1 = v1;
                    if (EPI == 1) {
                        a0 = fmaxf(a0 + bias[gn], 0.0f);
                        a1 = fmaxf(a1 + bias[gn + 1], 0.0f);
                    }
                    *reinterpret_cast<__half2*>(crow + gn) = __floats2half2_rn(a0, a1);
                } else {
                    float* crow = (float*)Cv + (size_t)gm * N;
                    if (EPI == 2) {
                        if (gn < N)     crow[gn]     = v0 + so2p[sob + gn] * ef;
                        if (gn + 1 < N) crow[gn + 1] = v1 + so2p[sob + gn + 1] * ef;
                    } else {
                        if (gn < N)     crow[gn]     = v0;
                        if (gn + 1 < N) crow[gn + 1] = v1;
                    }
                }
            }
        }
    }
}

// ---------------- host ----------------
extern "C" void kernel_launch(void* const* d_in, const int* in_sizes, int n_in,
                              void* d_out, int out_size)
{
    const float* inp_sf  = (const float*)d_in[0];
    const float* inp_of  = (const float*)d_in[1];
    const float* inp_ppf = (const float*)d_in[2];
    const float* inp_pvf = (const float*)d_in[3];
    const int*   gt_s    = (const int*)d_in[4];
    const int*   gt_o    = (const int*)d_in[5];
    const float* W_obj1  = (const float*)d_in[6];
    const float* b_obj1  = (const float*)d_in[7];
    const float* W_obj2  = (const float*)d_in[8];
    const float* W_pvf   = (const float*)d_in[9];
    const float* b_pvf   = (const float*)d_in[10];
    const float* W_pf    = (const float*)d_in[11];
    const float* b_pf    = (const float*)d_in[12];
    const float* W_pred  = (const float*)d_in[13];
    const float* so2p    = (const float*)d_in[14];
    const float* sof     = (const float*)d_in[15];

    float* out   = (float*)d_out;
    float* out_s = out;
    float* out_o = out + (size_t)BQ * OBJ_NUM;
    float* out_p = out + (size_t)2 * BQ * OBJ_NUM;

    __half *sfh, *ofh, *pvfh, *ppfh, *Hs, *Ho, *Hv, *Hp, *Wt1, *Wtv, *Wtf, *Wt2, *Wtp;
    cudaGetSymbolAddress((void**)&sfh,  g_sfh);
    cudaGetSymbolAddress((void**)&ofh,  g_ofh);
    cudaGetSymbolAddress((void**)&pvfh, g_pvfh);
    cudaGetSymbolAddress((void**)&ppfh, g_ppfh);
    cudaGetSymbolAddress((void**)&Hs,  g_Hs);
    cudaGetSymbolAddress((void**)&Ho,  g_Ho);
    cudaGetSymbolAddress((void**)&Hv,  g_Hv);
    cudaGetSymbolAddress((void**)&Hp,  g_Hp);
    cudaGetSymbolAddress((void**)&Wt1, g_Wt1);
    cudaGetSymbolAddress((void**)&Wtv, g_Wtv);
    cudaGetSymbolAddress((void**)&Wtf, g_Wtf);
    cudaGetSymbolAddress((void**)&Wt2, g_Wt2);
    cudaGetSymbolAddress((void**)&Wtp, g_Wtp);

    cudaFuncSetAttribute(mmagemm<1, false, true>,  cudaFuncAttributeMaxDynamicSharedMemorySize, SMEM_BYTES);
    cudaFuncSetAttribute(mmagemm<1, true,  true>,  cudaFuncAttributeMaxDynamicSharedMemorySize, SMEM_BYTES);
    cudaFuncSetAttribute(mmagemm<0, false, false>, cudaFuncAttributeMaxDynamicSharedMemorySize, SMEM_BYTES);
    cudaFuncSetAttribute(mmagemm<2, false, false>, cudaFuncAttributeMaxDynamicSharedMemorySize, SMEM_BYTES);

    // single fused prep launch (4 conversions + 5 transpose/pad/convert)
    prep<<<dim3(512, 1, 9), 256>>>(inp_sf, inp_of, inp_pvf, inp_ppf,
                                   sfh, ofh, pvfh, ppfh,
                                   W_obj1, W_pvf, W_pf, W_obj2, W_pred,
                                   Wt1, Wtv, Wtf, Wt2, Wtp);

    const dim3 blk(256);

    // stage 1: sf/of/pvf fused over z (K=1024, N=512)
    mmagemm<1, false, true><<<dim3(HIDDEN / 128, BQ / 128, 3), blk, SMEM_BYTES>>>(
        sfh, ofh, pvfh, nullptr, Wt1, Wtv, b_obj1, b_pvf,
        Hs, Ho, Hv, HIDDEN, OBJ_FEAT, nullptr, nullptr, nullptr, nullptr);

    // stage 2: pf_emb (concat Hv | ppf), K = 576
    mmagemm<1, true, true><<<dim3(HIDDEN / 128, BQ / 128, 1), blk, SMEM_BYTES>>>(
        Hv, Hv, Hv, ppfh, Wtf, Wtf, b_pf, b_pf,
        Hp, Hp, Hp, HIDDEN, HIDDEN + PPF_DIM, nullptr, nullptr, nullptr, nullptr);

    // stage 3a: s/o scores fused over z (K=512, N=1001 padded 1024)
    mmagemm<0, false, false><<<dim3(OBJ_PAD / 128, BQ / 128, 2), blk, SMEM_BYTES>>>(
        Hs, Ho, Ho, nullptr, Wt2, Wt2, nullptr, nullptr,
        out_s, out_o, out_o, OBJ_NUM, HIDDEN, nullptr, nullptr, nullptr, nullptr);

    // stage 3b: predicate scores + so2p gather (K=512, N=132 padded 256)
    mmagemm<2, false, false><<<dim3(PRED_PAD / 128, BQ / 128, 1), blk, SMEM_BYTES>>>(
        Hp, Hp, Hp, nullptr, Wtp, Wtp, nullptr, nullptr,
        out_p, out_p, out_p, PRED_NUM, HIDDEN, gt_s, gt_o, so2p, sof);
}